// round 4
// baseline (speedup 1.0000x reference)
#include <cuda_runtime.h>
#include <math.h>

// Problem constants
#define NB   16     // batch
#define C_IN 1024   // input channels
#define DI   512    // inner channels
#define NSP  1024   // spatial positions (32*32)

// Scratch (device globals: allocation-free per harness rules)
__device__ float g_tpg[(size_t)NB * 3 * DI * NSP];   // theta|phi|g per batch, each [DI][NSP]
__device__ float g_attn[(size_t)NB * NSP * NSP];     // attention matrix per batch
__device__ float g_y[(size_t)NB * NSP * DI];         // y = attn @ g^T, [NSP][DI] row-major

// ---------------------------------------------------------------------------
// Generic strided SGEMM: C[m,n] = alpha * sum_k A(m,k)*B(k,n) + bias[m] (+resid)
//   A(m,k) at A[m*sa_m + k*sa_k], B(k,n) at B[k*sb_k + n*sb_n]
//   C row-major with row stride sc_m (n-stride == 1). Batched via blockIdx.z.
// Template flags select which dim of A/B is unit-stride (for float4 loads):
//   AK  = true  -> A contiguous in k (sa_k==1), else contiguous in m (sa_m==1)
//   BNC = true  -> B contiguous in n (sb_n==1), else contiguous in k (sb_k==1)
// Requires M,N multiples of 128 and K multiple of 16 (true for all calls here).
// ---------------------------------------------------------------------------
template<bool AK, bool BNC>
__global__ __launch_bounds__(256) void gemm_k(
    const float* __restrict__ A, long long sa_m, long long sa_k, long long sa_b,
    const float* __restrict__ B, long long sb_k, long long sb_n, long long sb_b,
    float* __restrict__ C, long long sc_m, long long sc_b,
    const float* __restrict__ bias,
    const float* __restrict__ resid, long long sr_b,
    int K, float alpha)
{
    constexpr int BM = 128, BN = 128, BK = 16, TM = 8, TN = 8;
    __shared__ __align__(16) float As[BK][BM];
    __shared__ __align__(16) float Bs[BK][BN];

    const int b = blockIdx.z;
    A += (long long)b * sa_b;
    B += (long long)b * sb_b;
    C += (long long)b * sc_b;
    if (resid) resid += (long long)b * sr_b;

    const int m0 = blockIdx.y * BM;
    const int n0 = blockIdx.x * BN;
    const int tid = threadIdx.x;
    const int tx = tid & 15;   // N direction (16 threads)
    const int ty = tid >> 4;   // M direction (16 threads)

    float acc[TM][TN];
#pragma unroll
    for (int i = 0; i < TM; i++)
#pragma unroll
        for (int j = 0; j < TN; j++) acc[i][j] = 0.f;

    for (int k0 = 0; k0 < K; k0 += BK) {
        // ---- load A tile into As[k][m] ----
        if (AK) {
            // A contiguous in k: float4 along k, transpose into shared
#pragma unroll
            for (int it = 0; it < 2; ++it) {
                int idx = tid + it * 256;          // 0..511 over BM*BK/4
                int m   = idx >> 2;                // / (BK/4)
                int k4  = idx & 3;
                float4 v = *reinterpret_cast<const float4*>(
                    A + (long long)(m0 + m) * sa_m + (k0 + k4 * 4));
                As[k4 * 4 + 0][m] = v.x;
                As[k4 * 4 + 1][m] = v.y;
                As[k4 * 4 + 2][m] = v.z;
                As[k4 * 4 + 3][m] = v.w;
            }
        } else {
            // A contiguous in m: float4 along m, direct store
#pragma unroll
            for (int it = 0; it < 2; ++it) {
                int idx = tid + it * 256;
                int k   = idx >> 5;                // / (BM/4)
                int m4  = idx & 31;
                float4 v = *reinterpret_cast<const float4*>(
                    A + (long long)(k0 + k) * sa_k + (m0 + m4 * 4));
                *reinterpret_cast<float4*>(&As[k][m4 * 4]) = v;
            }
        }
        // ---- load B tile into Bs[k][n] ----
        if (BNC) {
#pragma unroll
            for (int it = 0; it < 2; ++it) {
                int idx = tid + it * 256;
                int k   = idx >> 5;
                int n4  = idx & 31;
                float4 v = *reinterpret_cast<const float4*>(
                    B + (long long)(k0 + k) * sb_k + (n0 + n4 * 4));
                *reinterpret_cast<float4*>(&Bs[k][n4 * 4]) = v;
            }
        } else {
            // B contiguous in k: float4 along k, transpose into shared
#pragma unroll
            for (int it = 0; it < 2; ++it) {
                int idx = tid + it * 256;
                int n   = idx >> 2;
                int k4  = idx & 3;
                float4 v = *reinterpret_cast<const float4*>(
                    B + (long long)(n0 + n) * sb_n + (k0 + k4 * 4));
                Bs[k4 * 4 + 0][n] = v.x;
                Bs[k4 * 4 + 1][n] = v.y;
                Bs[k4 * 4 + 2][n] = v.z;
                Bs[k4 * 4 + 3][n] = v.w;
            }
        }
        __syncthreads();

        // ---- compute ----
#pragma unroll
        for (int kk = 0; kk < BK; kk++) {
            float af[TM], bf[TN];
            *reinterpret_cast<float4*>(af)     = *reinterpret_cast<const float4*>(&As[kk][ty * TM]);
            *reinterpret_cast<float4*>(af + 4) = *reinterpret_cast<const float4*>(&As[kk][ty * TM + 4]);
            *reinterpret_cast<float4*>(bf)     = *reinterpret_cast<const float4*>(&Bs[kk][tx * TN]);
            *reinterpret_cast<float4*>(bf + 4) = *reinterpret_cast<const float4*>(&Bs[kk][tx * TN + 4]);
#pragma unroll
            for (int i = 0; i < TM; i++)
#pragma unroll
                for (int j = 0; j < TN; j++)
                    acc[i][j] = fmaf(af[i], bf[j], acc[i][j]);
        }
        __syncthreads();
    }

    // ---- epilogue ----
#pragma unroll
    for (int i = 0; i < TM; i++) {
        int m = m0 + ty * TM + i;
        float bv = bias ? bias[m] : 0.f;
        long long rowoff = (long long)m * sc_m + n0 + tx * TN;
#pragma unroll
        for (int j = 0; j < TN; j += 4) {
            float4 r;
            r.x = fmaf(alpha, acc[i][j + 0], bv);
            r.y = fmaf(alpha, acc[i][j + 1], bv);
            r.z = fmaf(alpha, acc[i][j + 2], bv);
            r.w = fmaf(alpha, acc[i][j + 3], bv);
            if (resid) {
                float4 xv = *reinterpret_cast<const float4*>(resid + rowoff + j);
                r.x += xv.x; r.y += xv.y; r.z += xv.z; r.w += xv.w;
            }
            *reinterpret_cast<float4*>(C + rowoff + j) = r;
        }
    }
}

// ---------------------------------------------------------------------------
// Row softmax over attn rows of length NSP=1024. One 256-thread block per row,
// 4 elements (one float4) per thread.
// ---------------------------------------------------------------------------
__global__ __launch_bounds__(256) void softmax_rows(float* __restrict__ attn)
{
    const long long row = blockIdx.x;
    float* p = attn + row * NSP;
    const int tid = threadIdx.x;
    __shared__ float red[8];

    float4 v = reinterpret_cast<float4*>(p)[tid];

    // max
    float mx = fmaxf(fmaxf(v.x, v.y), fmaxf(v.z, v.w));
#pragma unroll
    for (int o = 16; o > 0; o >>= 1)
        mx = fmaxf(mx, __shfl_xor_sync(0xffffffffu, mx, o));
    if ((tid & 31) == 0) red[tid >> 5] = mx;
    __syncthreads();
    float m_all = red[0];
#pragma unroll
    for (int w = 1; w < 8; w++) m_all = fmaxf(m_all, red[w]);
    __syncthreads();

    // exp + sum
    v.x = expf(v.x - m_all);
    v.y = expf(v.y - m_all);
    v.z = expf(v.z - m_all);
    v.w = expf(v.w - m_all);
    float s = v.x + v.y + v.z + v.w;
#pragma unroll
    for (int o = 16; o > 0; o >>= 1)
        s += __shfl_xor_sync(0xffffffffu, s, o);
    if ((tid & 31) == 0) red[tid >> 5] = s;
    __syncthreads();
    float s_all = 0.f;
#pragma unroll
    for (int w = 0; w < 8; w++) s_all += red[w];

    float inv = 1.f / s_all;
    v.x *= inv; v.y *= inv; v.z *= inv; v.w *= inv;
    reinterpret_cast<float4*>(p)[tid] = v;
}

// ---------------------------------------------------------------------------
// kernel_launch
// Inputs (metadata order): x, w_theta, b_theta, w_phi, b_phi, w_g, b_g, w_out, b_out
// ---------------------------------------------------------------------------
extern "C" void kernel_launch(void* const* d_in, const int* in_sizes, int n_in,
                              void* d_out, int out_size)
{
    (void)in_sizes; (void)n_in; (void)out_size;
    const float* x   = (const float*)d_in[0];
    const float* w_t = (const float*)d_in[1];
    const float* b_t = (const float*)d_in[2];
    const float* w_p = (const float*)d_in[3];
    const float* b_p = (const float*)d_in[4];
    const float* w_g = (const float*)d_in[5];
    const float* b_g = (const float*)d_in[6];
    const float* w_o = (const float*)d_in[7];
    const float* b_o = (const float*)d_in[8];
    float* out = (float*)d_out;

    float *tpg = nullptr, *attn = nullptr, *y = nullptr;
    cudaGetSymbolAddress((void**)&tpg,  g_tpg);
    cudaGetSymbolAddress((void**)&attn, g_attn);
    cudaGetSymbolAddress((void**)&y,    g_y);

    const long long SB_X = (long long)C_IN * NSP;   // per-batch x/out stride
    const long long SB_T = (long long)3 * DI * NSP; // per-batch tpg stride
    const long long SB_A = (long long)NSP * NSP;    // per-batch attn stride
    const long long SB_Y = (long long)NSP * DI;     // per-batch y stride
    dim3 blk(256);

    // --- projections: [DI x NSP] = W[DI x C_IN] @ x_b[C_IN x NSP] (+bias) ---
    gemm_k<true, true><<<dim3(NSP / 128, DI / 128, NB), blk>>>(
        w_t, C_IN, 1, 0,
        x,   NSP,  1, SB_X,
        tpg, NSP,  SB_T,
        b_t, nullptr, 0, C_IN, 1.f);
    gemm_k<true, true><<<dim3(NSP / 128, DI / 128, NB), blk>>>(
        w_p, C_IN, 1, 0,
        x,   NSP,  1, SB_X,
        tpg + (long long)DI * NSP, NSP, SB_T,
        b_p, nullptr, 0, C_IN, 1.f);
    gemm_k<true, true><<<dim3(NSP / 128, DI / 128, NB), blk>>>(
        w_g, C_IN, 1, 0,
        x,   NSP,  1, SB_X,
        tpg + (long long)2 * DI * NSP, NSP, SB_T,
        b_g, nullptr, 0, C_IN, 1.f);

    // --- scores: attn[i,j] = (1/sqrt(DI)) * sum_d theta[d,i] * phi[d,j] ---
    // A(m=i, k=d) = theta[d*NSP + i]  (m-contiguous)
    // B(k=d, n=j) = phi[d*NSP + j]    (n-contiguous)
    gemm_k<false, true><<<dim3(NSP / 128, NSP / 128, NB), blk>>>(
        tpg, 1, NSP, SB_T,
        tpg + (long long)DI * NSP, NSP, 1, SB_T,
        attn, NSP, SB_A,
        nullptr, nullptr, 0, DI, 1.0f / sqrtf((float)DI));

    // --- softmax over each attn row ---
    softmax_rows<<<NB * NSP, 256>>>(attn);

    // --- y[i,d] = sum_j attn[i,j] * g[d,j] ---
    // A(m=i, k=j) = attn row-major (k-contiguous)
    // B(k=j, n=d) = g[d*NSP + j]   (k-contiguous)
    gemm_k<true, false><<<dim3(DI / 128, NSP / 128, NB), blk>>>(
        attn, NSP, 1, SB_A,
        tpg + (long long)2 * DI * NSP, 1, NSP, SB_T,
        y, DI, SB_Y,
        nullptr, nullptr, 0, NSP, 1.f);

    // --- out[c,p] = x[c,p] + b_out[c] + sum_d w_out[c,d] * y[p,d] ---
    // A(m=c, k=d) = w_out row-major (k-contiguous)
    // B(k=d, n=p) = y[p*DI + d]     (k-contiguous)
    gemm_k<true, false><<<dim3(NSP / 128, C_IN / 128, NB), blk>>>(
        w_o, DI, 1, 0,
        y, 1, DI, SB_Y,
        out, NSP, SB_X,
        b_o, x, SB_X, DI, 1.f);
}

// round 6
// speedup vs baseline: 2.3702x; 2.3702x over previous
#include <cuda_runtime.h>
#include <math.h>
#include <stdint.h>

// Problem constants
#define NB   16     // batch
#define C_IN 1024   // input channels
#define DI   512    // inner channels
#define NSP  1024   // spatial positions (32*32)

// Scratch (device globals: allocation-free per harness rules)
__device__ float g_tpg[(size_t)NB * 3 * DI * NSP];   // theta|phi|g per batch, each [DI][NSP]
__device__ float g_attn[(size_t)NB * NSP * NSP];     // attention matrix per batch
__device__ float g_y[(size_t)NB * NSP * DI];         // y = attn @ g^T, [NSP][DI] row-major

// cvt.rna.tf32.f32 requires a b32 destination register (not .f32).
__device__ __forceinline__ float to_tf32(float x) {
    uint32_t r;
    asm("cvt.rna.tf32.f32 %0, %1;" : "=r"(r) : "f"(x));
    return __uint_as_float(r);
}

__device__ __forceinline__ void mma_tf32(
    float& c0, float& c1, float& c2, float& c3,
    uint32_t a0, uint32_t a1, uint32_t a2, uint32_t a3,
    uint32_t b0, uint32_t b1)
{
    asm volatile(
        "mma.sync.aligned.m16n8k8.row.col.f32.tf32.tf32.f32 "
        "{%0,%1,%2,%3}, {%4,%5,%6,%7}, {%8,%9}, {%0,%1,%2,%3};"
        : "+f"(c0), "+f"(c1), "+f"(c2), "+f"(c3)
        : "r"(a0), "r"(a1), "r"(a2), "r"(a3), "r"(b0), "r"(b1));
}

// ---------------------------------------------------------------------------
// tf32 tensor-core GEMM: C[m,n] = alpha * sum_k A(m,k)*B(k,n) + bias[m] (+resid)
//   A(m,k) at A[m*sa_m + k*sa_k], B(k,n) at B[k*sb_k + n*sb_n]
//   C row-major with row stride sc_m. Batched via blockIdx.z.
// Template flags select which dim of A/B is unit-stride (for float4 loads):
//   AK  = true  -> A contiguous in k, else contiguous in m
//   BNC = true  -> B contiguous in n, else contiguous in k
// Block tile 128x128xBK16, 256 threads = 8 warps (2 along M x 4 along N),
// warp tile 64x32 -> 4x4 m16n8k8 MMAs per k8 step.
// Shared strides = 136 (== 8 mod 32) -> conflict-free fragment LDS.
// Requires M,N multiples of 128 and K multiple of 16.
// ---------------------------------------------------------------------------
#define LDA 136
#define LDB 136

template<bool AK, bool BNC>
__global__ __launch_bounds__(256, 2) void gemm_tf32(
    const float* __restrict__ A, long long sa_m, long long sa_k, long long sa_b,
    const float* __restrict__ B, long long sb_k, long long sb_n, long long sb_b,
    float* __restrict__ C, long long sc_m, long long sc_b,
    const float* __restrict__ bias,
    const float* __restrict__ resid, long long sr_b,
    int K, float alpha)
{
    constexpr int BM = 128, BN = 128, BK = 16;
    __shared__ __align__(16) float As[BK * LDA];
    __shared__ __align__(16) float Bs[BK * LDB];

    const int b = blockIdx.z;
    A += (long long)b * sa_b;
    B += (long long)b * sb_b;
    C += (long long)b * sc_b;
    if (resid) resid += (long long)b * sr_b;

    const int m0 = blockIdx.y * BM;
    const int n0 = blockIdx.x * BN;
    const int tid = threadIdx.x;
    const int lane = tid & 31;
    const int warp = tid >> 5;
    const int warp_m = warp & 1;          // 0..1  (64 rows each)
    const int warp_n = warp >> 1;         // 0..3  (32 cols each)
    const int g = lane >> 2;              // groupID 0..7
    const int t = lane & 3;               // threadID_in_group 0..3

    float acc[4][4][4];                   // [mtile][ntile][frag]
#pragma unroll
    for (int i = 0; i < 4; i++)
#pragma unroll
        for (int j = 0; j < 4; j++)
#pragma unroll
            for (int f = 0; f < 4; f++) acc[i][j][f] = 0.f;

    for (int k0 = 0; k0 < K; k0 += BK) {
        // ---- load A tile into As[k*LDA + m] (tf32-converted) ----
        if (AK) {
#pragma unroll
            for (int it = 0; it < 2; ++it) {
                int idx = tid + it * 256;          // 0..511
                int m   = idx >> 2;
                int k4  = idx & 3;
                float4 v = *reinterpret_cast<const float4*>(
                    A + (long long)(m0 + m) * sa_m + (k0 + k4 * 4));
                As[(k4 * 4 + 0) * LDA + m] = to_tf32(v.x);
                As[(k4 * 4 + 1) * LDA + m] = to_tf32(v.y);
                As[(k4 * 4 + 2) * LDA + m] = to_tf32(v.z);
                As[(k4 * 4 + 3) * LDA + m] = to_tf32(v.w);
            }
        } else {
#pragma unroll
            for (int it = 0; it < 2; ++it) {
                int idx = tid + it * 256;
                int k   = idx >> 5;
                int m4  = idx & 31;
                float4 v = *reinterpret_cast<const float4*>(
                    A + (long long)(k0 + k) * sa_k + (m0 + m4 * 4));
                v.x = to_tf32(v.x); v.y = to_tf32(v.y);
                v.z = to_tf32(v.z); v.w = to_tf32(v.w);
                *reinterpret_cast<float4*>(&As[k * LDA + m4 * 4]) = v;
            }
        }
        // ---- load B tile into Bs[k*LDB + n] (tf32-converted) ----
        if (BNC) {
#pragma unroll
            for (int it = 0; it < 2; ++it) {
                int idx = tid + it * 256;
                int k   = idx >> 5;
                int n4  = idx & 31;
                float4 v = *reinterpret_cast<const float4*>(
                    B + (long long)(k0 + k) * sb_k + (n0 + n4 * 4));
                v.x = to_tf32(v.x); v.y = to_tf32(v.y);
                v.z = to_tf32(v.z); v.w = to_tf32(v.w);
                *reinterpret_cast<float4*>(&Bs[k * LDB + n4 * 4]) = v;
            }
        } else {
#pragma unroll
            for (int it = 0; it < 2; ++it) {
                int idx = tid + it * 256;
                int n   = idx >> 2;
                int k4  = idx & 3;
                float4 v = *reinterpret_cast<const float4*>(
                    B + (long long)(n0 + n) * sb_n + (k0 + k4 * 4));
                Bs[(k4 * 4 + 0) * LDB + n] = to_tf32(v.x);
                Bs[(k4 * 4 + 1) * LDB + n] = to_tf32(v.y);
                Bs[(k4 * 4 + 2) * LDB + n] = to_tf32(v.z);
                Bs[(k4 * 4 + 3) * LDB + n] = to_tf32(v.w);
            }
        }
        __syncthreads();

        // ---- compute: 2 k8 steps ----
#pragma unroll
        for (int kb = 0; kb < BK; kb += 8) {
            uint32_t af[4][4];
            uint32_t bf[4][2];
            const int mW = warp_m * 64;
            const int nW = warp_n * 32;
#pragma unroll
            for (int i = 0; i < 4; i++) {
                int mB = mW + i * 16;
                af[i][0] = __float_as_uint(As[(kb + t) * LDA + mB + g]);
                af[i][1] = __float_as_uint(As[(kb + t) * LDA + mB + g + 8]);
                af[i][2] = __float_as_uint(As[(kb + t + 4) * LDA + mB + g]);
                af[i][3] = __float_as_uint(As[(kb + t + 4) * LDA + mB + g + 8]);
            }
#pragma unroll
            for (int j = 0; j < 4; j++) {
                int nB = nW + j * 8;
                bf[j][0] = __float_as_uint(Bs[(kb + t) * LDB + nB + g]);
                bf[j][1] = __float_as_uint(Bs[(kb + t + 4) * LDB + nB + g]);
            }
#pragma unroll
            for (int i = 0; i < 4; i++)
#pragma unroll
                for (int j = 0; j < 4; j++)
                    mma_tf32(acc[i][j][0], acc[i][j][1], acc[i][j][2], acc[i][j][3],
                             af[i][0], af[i][1], af[i][2], af[i][3],
                             bf[j][0], bf[j][1]);
        }
        __syncthreads();
    }

    // ---- epilogue ----
    const int mW = m0 + warp_m * 64;
    const int nW = n0 + warp_n * 32;
#pragma unroll
    for (int i = 0; i < 4; i++) {
        int r0 = mW + i * 16 + g;
        int r1 = r0 + 8;
        float bv0 = bias ? bias[r0] : 0.f;
        float bv1 = bias ? bias[r1] : 0.f;
#pragma unroll
        for (int j = 0; j < 4; j++) {
            int cB = nW + j * 8 + 2 * t;
            float2 v0, v1;
            v0.x = fmaf(alpha, acc[i][j][0], bv0);
            v0.y = fmaf(alpha, acc[i][j][1], bv0);
            v1.x = fmaf(alpha, acc[i][j][2], bv1);
            v1.y = fmaf(alpha, acc[i][j][3], bv1);
            long long o0 = (long long)r0 * sc_m + cB;
            long long o1 = (long long)r1 * sc_m + cB;
            if (resid) {
                float2 x0 = *reinterpret_cast<const float2*>(resid + o0);
                float2 x1 = *reinterpret_cast<const float2*>(resid + o1);
                v0.x += x0.x; v0.y += x0.y;
                v1.x += x1.x; v1.y += x1.y;
            }
            *reinterpret_cast<float2*>(C + o0) = v0;
            *reinterpret_cast<float2*>(C + o1) = v1;
        }
    }
}

// ---------------------------------------------------------------------------
// Row softmax over attn rows of length NSP=1024. One 256-thread block per row.
// ---------------------------------------------------------------------------
__global__ __launch_bounds__(256) void softmax_rows(float* __restrict__ attn)
{
    const long long row = blockIdx.x;
    float* p = attn + row * NSP;
    const int tid = threadIdx.x;
    __shared__ float red[8];

    float4 v = reinterpret_cast<float4*>(p)[tid];

    float mx = fmaxf(fmaxf(v.x, v.y), fmaxf(v.z, v.w));
#pragma unroll
    for (int o = 16; o > 0; o >>= 1)
        mx = fmaxf(mx, __shfl_xor_sync(0xffffffffu, mx, o));
    if ((tid & 31) == 0) red[tid >> 5] = mx;
    __syncthreads();
    float m_all = red[0];
#pragma unroll
    for (int w = 1; w < 8; w++) m_all = fmaxf(m_all, red[w]);
    __syncthreads();

    v.x = expf(v.x - m_all);
    v.y = expf(v.y - m_all);
    v.z = expf(v.z - m_all);
    v.w = expf(v.w - m_all);
    float s = v.x + v.y + v.z + v.w;
#pragma unroll
    for (int o = 16; o > 0; o >>= 1)
        s += __shfl_xor_sync(0xffffffffu, s, o);
    if ((tid & 31) == 0) red[tid >> 5] = s;
    __syncthreads();
    float s_all = 0.f;
#pragma unroll
    for (int w = 0; w < 8; w++) s_all += red[w];

    float inv = 1.f / s_all;
    v.x *= inv; v.y *= inv; v.z *= inv; v.w *= inv;
    reinterpret_cast<float4*>(p)[tid] = v;
}

// ---------------------------------------------------------------------------
// kernel_launch
// Inputs (metadata order): x, w_theta, b_theta, w_phi, b_phi, w_g, b_g, w_out, b_out
// ---------------------------------------------------------------------------
extern "C" void kernel_launch(void* const* d_in, const int* in_sizes, int n_in,
                              void* d_out, int out_size)
{
    (void)in_sizes; (void)n_in; (void)out_size;
    const float* x   = (const float*)d_in[0];
    const float* w_t = (const float*)d_in[1];
    const float* b_t = (const float*)d_in[2];
    const float* w_p = (const float*)d_in[3];
    const float* b_p = (const float*)d_in[4];
    const float* w_g = (const float*)d_in[5];
    const float* b_g = (const float*)d_in[6];
    const float* w_o = (const float*)d_in[7];
    const float* b_o = (const float*)d_in[8];
    float* out = (float*)d_out;

    float *tpg = nullptr, *attn = nullptr, *y = nullptr;
    cudaGetSymbolAddress((void**)&tpg,  g_tpg);
    cudaGetSymbolAddress((void**)&attn, g_attn);
    cudaGetSymbolAddress((void**)&y,    g_y);

    const long long SB_X = (long long)C_IN * NSP;   // per-batch x/out stride
    const long long SB_T = (long long)3 * DI * NSP; // per-batch tpg stride
    const long long SB_A = (long long)NSP * NSP;    // per-batch attn stride
    const long long SB_Y = (long long)NSP * DI;     // per-batch y stride
    dim3 blk(256);

    // --- projections: [DI x NSP] = W[DI x C_IN] @ x_b[C_IN x NSP] (+bias) ---
    gemm_tf32<true, true><<<dim3(NSP / 128, DI / 128, NB), blk>>>(
        w_t, C_IN, 1, 0,
        x,   NSP,  1, SB_X,
        tpg, NSP,  SB_T,
        b_t, nullptr, 0, C_IN, 1.f);
    gemm_tf32<true, true><<<dim3(NSP / 128, DI / 128, NB), blk>>>(
        w_p, C_IN, 1, 0,
        x,   NSP,  1, SB_X,
        tpg + (long long)DI * NSP, NSP, SB_T,
        b_p, nullptr, 0, C_IN, 1.f);
    gemm_tf32<true, true><<<dim3(NSP / 128, DI / 128, NB), blk>>>(
        w_g, C_IN, 1, 0,
        x,   NSP,  1, SB_X,
        tpg + (long long)2 * DI * NSP, NSP, SB_T,
        b_g, nullptr, 0, C_IN, 1.f);

    // --- scores: attn[i,j] = (1/sqrt(DI)) * sum_d theta[d,i] * phi[d,j] ---
    gemm_tf32<false, true><<<dim3(NSP / 128, NSP / 128, NB), blk>>>(
        tpg, 1, NSP, SB_T,
        tpg + (long long)DI * NSP, NSP, 1, SB_T,
        attn, NSP, SB_A,
        nullptr, nullptr, 0, DI, 1.0f / sqrtf((float)DI));

    // --- softmax over each attn row ---
    softmax_rows<<<NB * NSP, 256>>>(attn);

    // --- y[i,d] = sum_j attn[i,j] * g[d,j] ---
    gemm_tf32<true, false><<<dim3(DI / 128, NSP / 128, NB), blk>>>(
        attn, NSP, 1, SB_A,
        tpg + (long long)2 * DI * NSP, 1, NSP, SB_T,
        y, DI, SB_Y,
        nullptr, nullptr, 0, NSP, 1.f);

    // --- out[c,p] = x[c,p] + b_out[c] + sum_d w_out[c,d] * y[p,d] ---
    gemm_tf32<true, false><<<dim3(NSP / 128, C_IN / 128, NB), blk>>>(
        w_o, DI, 1, 0,
        y, 1, DI, SB_Y,
        out, NSP, SB_X,
        b_o, x, SB_X, DI, 1.f);
}

// round 7
// speedup vs baseline: 5.0325x; 2.1232x over previous
#include <cuda_runtime.h>
#include <cuda_bf16.h>
#include <math.h>
#include <stdint.h>

// Problem constants
#define NB   16     // batch
#define C_IN 1024   // input channels
#define DI   512    // inner channels
#define NSP  1024   // spatial positions (32*32)

// ---------------------------------------------------------------------------
// Scratch (device globals: allocation-free per harness rules)
// ---------------------------------------------------------------------------
__device__ __nv_bfloat16 g_xT[(size_t)NB * NSP * C_IN];      // x^T per batch [p][c]
__device__ __nv_bfloat16 g_wt[(size_t)DI * C_IN];
__device__ __nv_bfloat16 g_wp[(size_t)DI * C_IN];
__device__ __nv_bfloat16 g_wg[(size_t)DI * C_IN];
__device__ __nv_bfloat16 g_wo[(size_t)C_IN * DI];
__device__ __nv_bfloat16 g_th[(size_t)NB * NSP * DI];        // theta [p][d]
__device__ __nv_bfloat16 g_ph[(size_t)NB * NSP * DI];        // phi   [p][d]
__device__ __nv_bfloat16 g_gg[(size_t)NB * NSP * DI];        // g     [p][d]
__device__ __nv_bfloat16 g_gT[(size_t)NB * DI * NSP];        // g^T   [d][p]
__device__ float         g_attn[(size_t)NB * NSP * NSP];     // scores fp32
__device__ __nv_bfloat16 g_attn_bf[(size_t)NB * NSP * NSP];  // probs bf16
__device__ __nv_bfloat16 g_y[(size_t)NB * NSP * DI];         // y [i][d]

// ---------------------------------------------------------------------------
// cp.async helpers
// ---------------------------------------------------------------------------
__device__ __forceinline__ void cpa16(void* s, const void* g) {
    uint32_t sa = (uint32_t)__cvta_generic_to_shared(s);
    asm volatile("cp.async.cg.shared.global [%0], [%1], 16;\n" :: "r"(sa), "l"(g));
}
#define CP_COMMIT() asm volatile("cp.async.commit_group;\n" ::: "memory")
#define CP_WAIT1()  asm volatile("cp.async.wait_group 1;\n" ::: "memory")

__device__ __forceinline__ void mma_bf16(
    float& c0, float& c1, float& c2, float& c3,
    uint32_t a0, uint32_t a1, uint32_t a2, uint32_t a3,
    uint32_t b0, uint32_t b1)
{
    asm volatile(
        "mma.sync.aligned.m16n8k16.row.col.f32.bf16.bf16.f32 "
        "{%0,%1,%2,%3}, {%4,%5,%6,%7}, {%8,%9}, {%0,%1,%2,%3};"
        : "+f"(c0), "+f"(c1), "+f"(c2), "+f"(c3)
        : "r"(a0), "r"(a1), "r"(a2), "r"(a3), "r"(b0), "r"(b1));
}

// ---------------------------------------------------------------------------
// bf16 NT GEMM: C[m,n] = alpha * sum_k A[m][k]*B[n][k] (+bias) (+resid)
//   A: bf16 [M][K] row stride lda (k-contiguous). B: bf16 [N][K] stride ldb.
//   C: bf16 (OUT_BF16) or fp32. bias fp32 along m (BIAS_N=false) or n (true).
//   resid: fp32, same layout as C (fp32 path only). Batched via blockIdx.z.
// Block tile 128x128xBK32, 256 thr = 8 warps (2M x 4N), warp tile 64x32.
// 2-stage cp.async pipeline. Requires M,N mult of 128, K mult of 32.
// Shared rows padded to 40 bf16 (20 words) -> conflict-free fragment LDS.
// ---------------------------------------------------------------------------
#define BKT 32
#define LDK 40

template<bool OUT_BF16, bool BIAS_N>
__global__ __launch_bounds__(256, 2) void gemm_bf16_nt(
    const __nv_bfloat16* __restrict__ A, long long lda, long long sa_b,
    const __nv_bfloat16* __restrict__ B, long long ldb, long long sb_b,
    void* __restrict__ Cv, long long ldc, long long sc_b,
    const float* __restrict__ bias,
    const float* __restrict__ resid, long long sr_b,
    int K, float alpha)
{
    __shared__ __align__(16) __nv_bfloat16 As[2][128][LDK];
    __shared__ __align__(16) __nv_bfloat16 Bs[2][128][LDK];

    const int b = blockIdx.z;
    A += (long long)b * sa_b;
    B += (long long)b * sb_b;
    if (resid) resid += (long long)b * sr_b;

    const int m0 = blockIdx.y * 128;
    const int n0 = blockIdx.x * 128;
    const int tid = threadIdx.x;
    const int lane = tid & 31;
    const int warp = tid >> 5;
    const int warp_m = warp & 1;
    const int warp_n = warp >> 1;
    const int g = lane >> 2;
    const int t = lane & 3;

    float acc[4][4][4];
#pragma unroll
    for (int i = 0; i < 4; i++)
#pragma unroll
        for (int j = 0; j < 4; j++)
#pragma unroll
            for (int f = 0; f < 4; f++) acc[i][j][f] = 0.f;

    const int KT = K / BKT;

    // stage loader: each thread copies 2x16B for A and 2x16B for B
    auto load_stage = [&](int s, int k0) {
#pragma unroll
        for (int it = 0; it < 2; ++it) {
            int id = tid + it * 256;        // 0..511
            int r  = id >> 2;               // row 0..127
            int c  = id & 3;                // 16B chunk (8 bf16)
            cpa16(&As[s][r][c * 8], A + (long long)(m0 + r) * lda + k0 + c * 8);
        }
#pragma unroll
        for (int it = 0; it < 2; ++it) {
            int id = tid + it * 256;
            int r  = id >> 2;
            int c  = id & 3;
            cpa16(&Bs[s][r][c * 8], B + (long long)(n0 + r) * ldb + k0 + c * 8);
        }
    };

    load_stage(0, 0);
    CP_COMMIT();

    for (int kt = 0; kt < KT; kt++) {
        if (kt + 1 < KT) load_stage((kt + 1) & 1, (kt + 1) * BKT);
        CP_COMMIT();
        CP_WAIT1();
        __syncthreads();

        const int s = kt & 1;
        const int mW = warp_m * 64;
        const int nW = warp_n * 32;
#pragma unroll
        for (int ks = 0; ks < 2; ks++) {
            const int kb = ks * 16;
            uint32_t af[4][4], bf[4][2];
#pragma unroll
            for (int i = 0; i < 4; i++) {
                int mB = mW + i * 16;
                af[i][0] = *reinterpret_cast<const uint32_t*>(&As[s][mB + g    ][kb + 2 * t]);
                af[i][1] = *reinterpret_cast<const uint32_t*>(&As[s][mB + g + 8][kb + 2 * t]);
                af[i][2] = *reinterpret_cast<const uint32_t*>(&As[s][mB + g    ][kb + 2 * t + 8]);
                af[i][3] = *reinterpret_cast<const uint32_t*>(&As[s][mB + g + 8][kb + 2 * t + 8]);
            }
#pragma unroll
            for (int j = 0; j < 4; j++) {
                int nB = nW + j * 8;
                bf[j][0] = *reinterpret_cast<const uint32_t*>(&Bs[s][nB + g][kb + 2 * t]);
                bf[j][1] = *reinterpret_cast<const uint32_t*>(&Bs[s][nB + g][kb + 2 * t + 8]);
            }
#pragma unroll
            for (int i = 0; i < 4; i++)
#pragma unroll
                for (int j = 0; j < 4; j++)
                    mma_bf16(acc[i][j][0], acc[i][j][1], acc[i][j][2], acc[i][j][3],
                             af[i][0], af[i][1], af[i][2], af[i][3],
                             bf[j][0], bf[j][1]);
        }
        __syncthreads();
    }

    // ---- epilogue ----
    const int mW = m0 + warp_m * 64;
    const int nW = n0 + warp_n * 32;
#pragma unroll
    for (int i = 0; i < 4; i++) {
        int r0 = mW + i * 16 + g;
        int r1 = r0 + 8;
        float bm0 = 0.f, bm1 = 0.f;
        if (!BIAS_N && bias) { bm0 = bias[r0]; bm1 = bias[r1]; }
#pragma unroll
        for (int j = 0; j < 4; j++) {
            int col = nW + j * 8 + 2 * t;
            float bn0 = 0.f, bn1 = 0.f;
            if (BIAS_N && bias) { bn0 = bias[col]; bn1 = bias[col + 1]; }
            float v00 = fmaf(alpha, acc[i][j][0], BIAS_N ? bn0 : bm0);
            float v01 = fmaf(alpha, acc[i][j][1], BIAS_N ? bn1 : bm0);
            float v10 = fmaf(alpha, acc[i][j][2], BIAS_N ? bn0 : bm1);
            float v11 = fmaf(alpha, acc[i][j][3], BIAS_N ? bn1 : bm1);
            long long o0 = (long long)r0 * ldc + col;
            long long o1 = (long long)r1 * ldc + col;
            if (OUT_BF16) {
                __nv_bfloat16* Cb = (__nv_bfloat16*)Cv + (long long)b * sc_b;
                *reinterpret_cast<__nv_bfloat162*>(Cb + o0) = __floats2bfloat162_rn(v00, v01);
                *reinterpret_cast<__nv_bfloat162*>(Cb + o1) = __floats2bfloat162_rn(v10, v11);
            } else {
                float* Cf = (float*)Cv + (long long)b * sc_b;
                float2 w0 = make_float2(v00, v01);
                float2 w1 = make_float2(v10, v11);
                if (resid) {
                    float2 x0 = *reinterpret_cast<const float2*>(resid + o0);
                    float2 x1 = *reinterpret_cast<const float2*>(resid + o1);
                    w0.x += x0.x; w0.y += x0.y;
                    w1.x += x1.x; w1.y += x1.y;
                }
                *reinterpret_cast<float2*>(Cf + o0) = w0;
                *reinterpret_cast<float2*>(Cf + o1) = w1;
            }
        }
    }
}

// ---------------------------------------------------------------------------
// Layout/conversion prep kernels
// ---------------------------------------------------------------------------
__global__ void f2bf(const float* __restrict__ in, __nv_bfloat16* __restrict__ out, int n)
{
    int i = blockIdx.x * 256 + threadIdx.x;
    if (i < n) out[i] = __float2bfloat16(in[i]);
}

// x [b][c][p] fp32 -> xT [b][p][c] bf16
__global__ void transpose_convert_x(const float* __restrict__ x, __nv_bfloat16* __restrict__ xT)
{
    __shared__ float sh[32][33];
    int bz = blockIdx.z;
    int c0 = blockIdx.y * 32, p0 = blockIdx.x * 32;
    const float* xb = x + (long long)bz * C_IN * NSP;
    __nv_bfloat16* xo = xT + (long long)bz * NSP * C_IN;
    int tx = threadIdx.x, ty = threadIdx.y;
#pragma unroll
    for (int i = 0; i < 32; i += 8)
        sh[ty + i][tx] = xb[(long long)(c0 + ty + i) * NSP + p0 + tx];
    __syncthreads();
#pragma unroll
    for (int i = 0; i < 32; i += 8)
        xo[(long long)(p0 + ty + i) * C_IN + c0 + tx] = __float2bfloat16(sh[tx][ty + i]);
}

// g [b][p][d] bf16 -> gT [b][d][p] bf16
__global__ void transpose_g(const __nv_bfloat16* __restrict__ gi, __nv_bfloat16* __restrict__ go)
{
    __shared__ __nv_bfloat16 sh[32][33];
    int bz = blockIdx.z;
    int p0 = blockIdx.x * 32, d0 = blockIdx.y * 32;
    const __nv_bfloat16* gb = gi + (long long)bz * NSP * DI;
    __nv_bfloat16* gt = go + (long long)bz * DI * NSP;
    int tx = threadIdx.x, ty = threadIdx.y;
#pragma unroll
    for (int i = 0; i < 32; i += 8)
        sh[ty + i][tx] = gb[(long long)(p0 + ty + i) * DI + d0 + tx];
    __syncthreads();
#pragma unroll
    for (int i = 0; i < 32; i += 8)
        gt[(long long)(d0 + ty + i) * NSP + p0 + tx] = sh[tx][ty + i];
}

// ---------------------------------------------------------------------------
// Row softmax: fp32 scores in, bf16 probs out. One 256-thread block per row.
// ---------------------------------------------------------------------------
__global__ __launch_bounds__(256) void softmax_rows(
    const float* __restrict__ attn, __nv_bfloat16* __restrict__ probs)
{
    const long long row = blockIdx.x;
    const float* p = attn + row * NSP;
    __nv_bfloat16* q = probs + row * NSP;
    const int tid = threadIdx.x;
    __shared__ float red[8];

    float4 v = reinterpret_cast<const float4*>(p)[tid];

    float mx = fmaxf(fmaxf(v.x, v.y), fmaxf(v.z, v.w));
#pragma unroll
    for (int o = 16; o > 0; o >>= 1)
        mx = fmaxf(mx, __shfl_xor_sync(0xffffffffu, mx, o));
    if ((tid & 31) == 0) red[tid >> 5] = mx;
    __syncthreads();
    float m_all = red[0];
#pragma unroll
    for (int w = 1; w < 8; w++) m_all = fmaxf(m_all, red[w]);
    __syncthreads();

    v.x = expf(v.x - m_all);
    v.y = expf(v.y - m_all);
    v.z = expf(v.z - m_all);
    v.w = expf(v.w - m_all);
    float s = v.x + v.y + v.z + v.w;
#pragma unroll
    for (int o = 16; o > 0; o >>= 1)
        s += __shfl_xor_sync(0xffffffffu, s, o);
    if ((tid & 31) == 0) red[tid >> 5] = s;
    __syncthreads();
    float s_all = 0.f;
#pragma unroll
    for (int w = 0; w < 8; w++) s_all += red[w];

    float inv = 1.f / s_all;
    reinterpret_cast<__nv_bfloat162*>(q)[2 * tid]     = __floats2bfloat162_rn(v.x * inv, v.y * inv);
    reinterpret_cast<__nv_bfloat162*>(q)[2 * tid + 1] = __floats2bfloat162_rn(v.z * inv, v.w * inv);
}

// ---------------------------------------------------------------------------
// kernel_launch
// Inputs (metadata order): x, w_theta, b_theta, w_phi, b_phi, w_g, b_g, w_out, b_out
// ---------------------------------------------------------------------------
extern "C" void kernel_launch(void* const* d_in, const int* in_sizes, int n_in,
                              void* d_out, int out_size)
{
    (void)in_sizes; (void)n_in; (void)out_size;
    const float* x   = (const float*)d_in[0];
    const float* w_t = (const float*)d_in[1];
    const float* b_t = (const float*)d_in[2];
    const float* w_p = (const float*)d_in[3];
    const float* b_p = (const float*)d_in[4];
    const float* w_g = (const float*)d_in[5];
    const float* b_g = (const float*)d_in[6];
    const float* w_o = (const float*)d_in[7];
    const float* b_o = (const float*)d_in[8];
    float* out = (float*)d_out;

    __nv_bfloat16 *xT, *wt, *wp, *wg, *wo, *th, *ph, *gg, *gT, *attn_bf, *y;
    float* attn;
    cudaGetSymbolAddress((void**)&xT, g_xT);
    cudaGetSymbolAddress((void**)&wt, g_wt);
    cudaGetSymbolAddress((void**)&wp, g_wp);
    cudaGetSymbolAddress((void**)&wg, g_wg);
    cudaGetSymbolAddress((void**)&wo, g_wo);
    cudaGetSymbolAddress((void**)&th, g_th);
    cudaGetSymbolAddress((void**)&ph, g_ph);
    cudaGetSymbolAddress((void**)&gg, g_gg);
    cudaGetSymbolAddress((void**)&gT, g_gT);
    cudaGetSymbolAddress((void**)&attn, g_attn);
    cudaGetSymbolAddress((void**)&attn_bf, g_attn_bf);
    cudaGetSymbolAddress((void**)&y, g_y);

    const long long SB_X  = (long long)C_IN * NSP;
    const long long SB_PD = (long long)NSP * DI;   // [p][d] per batch
    const long long SB_A  = (long long)NSP * NSP;
    dim3 blk(256);

    // --- prep: weight conversion + x transpose ---
    const int NW = DI * C_IN;
    f2bf<<<(NW + 255) / 256, 256>>>(w_t, wt, NW);
    f2bf<<<(NW + 255) / 256, 256>>>(w_p, wp, NW);
    f2bf<<<(NW + 255) / 256, 256>>>(w_g, wg, NW);
    f2bf<<<(NW + 255) / 256, 256>>>(w_o, wo, NW);
    transpose_convert_x<<<dim3(32, 32, NB), dim3(32, 8)>>>(x, xT);

    // --- projections: C[p][di] = xT[p][c] @ W[di][c]^T (+bias along n=di) ---
    gemm_bf16_nt<true, true><<<dim3(DI / 128, NSP / 128, NB), blk>>>(
        xT, C_IN, SB_X, wt, C_IN, 0,
        th, DI, SB_PD, b_t, nullptr, 0, C_IN, 1.f);
    gemm_bf16_nt<true, true><<<dim3(DI / 128, NSP / 128, NB), blk>>>(
        xT, C_IN, SB_X, wp, C_IN, 0,
        ph, DI, SB_PD, b_p, nullptr, 0, C_IN, 1.f);
    gemm_bf16_nt<true, true><<<dim3(DI / 128, NSP / 128, NB), blk>>>(
        xT, C_IN, SB_X, wg, C_IN, 0,
        gg, DI, SB_PD, b_g, nullptr, 0, C_IN, 1.f);

    // --- transpose g -> gT[d][p] ---
    transpose_g<<<dim3(NSP / 32, DI / 32, NB), dim3(32, 8)>>>(gg, gT);

    // --- scores: attn[i][j] = alpha * theta[i][:]·phi[j][:]  (fp32 out) ---
    gemm_bf16_nt<false, false><<<dim3(NSP / 128, NSP / 128, NB), blk>>>(
        th, DI, SB_PD, ph, DI, SB_PD,
        attn, NSP, SB_A, nullptr, nullptr, 0, DI, 1.0f / sqrtf((float)DI));

    // --- softmax rows: fp32 -> bf16 probs ---
    softmax_rows<<<NB * NSP, 256>>>(attn, attn_bf);

    // --- y[i][d] = probs[i][:]·gT[d][:]  (bf16 out) ---
    gemm_bf16_nt<true, false><<<dim3(DI / 128, NSP / 128, NB), blk>>>(
        attn_bf, NSP, SB_A, gT, NSP, SB_PD,
        y, DI, SB_PD, nullptr, nullptr, 0, NSP, 1.f);

    // --- out[c][p] = x[c][p] + b_out[c] + w_out[c][:]·y[p][:]  (fp32 out) ---
    gemm_bf16_nt<false, false><<<dim3(NSP / 128, C_IN / 128, NB), blk>>>(
        wo, DI, 0, y, DI, SB_PD,
        out, NSP, SB_X, b_o, x, SB_X, DI, 1.f);
}